// round 6
// baseline (speedup 1.0000x reference)
#include <cuda_runtime.h>
#include <cuda_fp16.h>

#define NN 100000

// ---------------- device scratch (no allocations allowed) ----------------
__device__ __align__(16) __half2 g_hs16[NN * 32];   // h1*dinv as fp16 [N,64]
__device__ __align__(16) float4 g_agg[NN * 16];     // layer1 aggregate fp32
__device__ __align__(16) __half2 g_h2s16[NN * 8];   // h2*dinv as fp16 [N,16]
__device__ __align__(16) float4 g_oacc[NN * 4];     // layer2 aggregate fp32
__device__ unsigned g_deg[NN];                      // zero-init; finalize re-zeros
__device__ float g_dinv[NN];

// vectorized fp32 global reduction (sm_90+)
__device__ __forceinline__ void red4(float4* a, float4 v) {
    asm volatile("red.global.add.v4.f32 [%0], {%1,%2,%3,%4};" ::
                 "l"(a), "f"(v.x), "f"(v.y), "f"(v.z), "f"(v.w) : "memory");
}

// int64-vs-int32 detection (full-warp). Little-endian int64 with ids<100000
// => every odd int32 slot is 0. For int32 input odd slots are random ids.
__device__ __forceinline__ bool detect64(const int* __restrict__ e32) {
    int v = __ldg(&e32[2 * (threadIdx.x & 31) + 1]);
    return __ballot_sync(0xffffffffu, v != 0) == 0u;
}

__device__ __forceinline__ int load_idx(const int* __restrict__ e32, int i, bool is64) {
    return __ldg(&e32[is64 ? 2 * (long long)i : (long long)i]);
}
__device__ __forceinline__ int load_idx2(const int* __restrict__ e32, int E, int i,
                                         bool is64) {
    return __ldg(&e32[is64 ? 2 * ((long long)E + i) : (long long)(E + i)]);
}

// ---------------- degree count ----------------
__global__ void deg_count_kernel(const int* __restrict__ e32, int E) {
    bool is64 = detect64(e32);
    int t = blockIdx.x * blockDim.x + threadIdx.x;
    if (t >= E) return;
    int c = load_idx2(e32, E, t, is64);
    atomicAdd(&g_deg[c], 1u);
}

// ---------------- small GEMM helpers ----------------
template <int NJ>
__device__ __forceinline__ void fma_row(float4* acc, float xs, const float4* wr) {
#pragma unroll
    for (int j = 0; j < NJ; j++) {
        float4 w = wr[j];
        acc[j].x = fmaf(xs, w.x, acc[j].x);
        acc[j].y = fmaf(xs, w.y, acc[j].y);
        acc[j].z = fmaf(xs, w.z, acc[j].z);
        acc[j].w = fmaf(xs, w.w, acc[j].w);
    }
}

// mm1: 2 threads per row; each computes 32 output cols.
// dinv = rsqrt(deg+1); hs16 = (x@W1)*dinv (fp16); agg init = same in fp32.
__global__ void __launch_bounds__(256) mm1_kernel(const float4* __restrict__ X4,
                                                  const float* __restrict__ W) {
    __shared__ float4 sW[64 * 16];  // W1: 64x64 floats
    for (int i = threadIdx.x; i < 64 * 16; i += 256) sW[i] = ((const float4*)W)[i];
    __syncthreads();
    int t = blockIdx.x * 256 + threadIdx.x;
    int row = t >> 1;
    int half = t & 1;
    if (row >= NN) return;

    float dv = rsqrtf((float)(g_deg[row] + 1u));  // read-only here
    if (half == 0) g_dinv[row] = dv;

    float4 acc[8];
#pragma unroll
    for (int j = 0; j < 8; j++) acc[j] = make_float4(0.f, 0.f, 0.f, 0.f);
    const float4* wbase = &sW[half * 8];
#pragma unroll 4
    for (int k4 = 0; k4 < 16; k4++) {
        float4 xv = __ldg(&X4[(long long)row * 16 + k4]);
        fma_row<8>(acc, xv.x, wbase + (k4 * 4 + 0) * 16);
        fma_row<8>(acc, xv.y, wbase + (k4 * 4 + 1) * 16);
        fma_row<8>(acc, xv.z, wbase + (k4 * 4 + 2) * 16);
        fma_row<8>(acc, xv.w, wbase + (k4 * 4 + 3) * 16);
    }
    // Pack pairs of float4 (8 floats = 4 __half2 = one uint4) and store.
    // Layout: col c lives at __half2 slot c/2; this thread covers cols
    // [half*32 + 4j, half*32 + 4j+3] -> slots half*16 + 2j .. 2j+3.
    union { __half2 h[4]; uint4 u; } pk;
#pragma unroll
    for (int j = 0; j < 8; j++) {
        float4 v = make_float4(acc[j].x * dv, acc[j].y * dv, acc[j].z * dv, acc[j].w * dv);
        g_agg[row * 16 + half * 8 + j] = v;
        pk.h[(j & 1) * 2 + 0] = __floats2half2_rn(v.x, v.y);
        pk.h[(j & 1) * 2 + 1] = __floats2half2_rn(v.z, v.w);
        if (j & 1)
            *(uint4*)&g_hs16[row * 32 + half * 16 + (j - 1) * 2] = pk.u;
    }
}

// ---------------- edge scatter, layer 1 ----------------
// Warp strip-mines 32 edges; 16 lanes/edge, each lane: 8B fp16 gather -> fp32 RED.128.
__global__ void __launch_bounds__(256) scatter1_kernel(const int* __restrict__ e32,
                                                       int E) {
    bool is64 = detect64(e32);
    int lane = threadIdx.x & 31;
    int warp = (blockIdx.x * blockDim.x + threadIdx.x) >> 5;
    int base = warp * 32;
    if (base >= E) return;
    int ed = base + lane;
    int edc = ed < E ? ed : E - 1;  // clamp, keep full-warp loads
    int r_l = load_idx(e32, edc, is64);
    int c_l = load_idx2(e32, E, edc, is64);
    int q = lane & 15;
    int sub = lane >> 4;
#pragma unroll
    for (int j = 0; j < 16; j++) {
        int e0 = 2 * j + sub;
        int rr = __shfl_sync(0xffffffffu, r_l, e0);
        int cc = __shfl_sync(0xffffffffu, c_l, e0);
        if (base + e0 < E) {
            uint2 u = __ldg((const uint2*)&g_hs16[rr * 32 + 2 * q]);
            __half2 h0 = *(__half2*)&u.x;
            __half2 h1 = *(__half2*)&u.y;
            float2 f0 = __half22float2(h0);
            float2 f1 = __half22float2(h1);
            red4(&g_agg[cc * 16 + q], make_float4(f0.x, f0.y, f1.x, f1.y));
        }
    }
}

// mm2: 2 threads/row; a = agg*dinv + b1, relu; h2 = a@W2; h2s16 = h2*dinv; oacc = same.
__global__ void __launch_bounds__(256) mm2_kernel(const float* __restrict__ W2,
                                                  const float* __restrict__ b1) {
    __shared__ float4 sW[64 * 4];  // W2: 64x16 floats
    __shared__ float4 sB1[16];
    for (int i = threadIdx.x; i < 64 * 4; i += 256) sW[i] = ((const float4*)W2)[i];
    if (threadIdx.x < 16) sB1[threadIdx.x] = ((const float4*)b1)[threadIdx.x];
    __syncthreads();
    int t = blockIdx.x * 256 + threadIdx.x;
    int row = t >> 1;
    int half = t & 1;
    if (row >= NN) return;
    float dv = g_dinv[row];
    float4 acc[2];
    acc[0] = make_float4(0.f, 0.f, 0.f, 0.f);
    acc[1] = make_float4(0.f, 0.f, 0.f, 0.f);
    const float4* wbase = &sW[half * 2];
#pragma unroll 4
    for (int k4 = 0; k4 < 16; k4++) {
        float4 a = g_agg[row * 16 + k4];
        float4 bb = sB1[k4];
        a.x = fmaxf(fmaf(a.x, dv, bb.x), 0.f);
        a.y = fmaxf(fmaf(a.y, dv, bb.y), 0.f);
        a.z = fmaxf(fmaf(a.z, dv, bb.z), 0.f);
        a.w = fmaxf(fmaf(a.w, dv, bb.w), 0.f);
        fma_row<2>(acc, a.x, wbase + (k4 * 4 + 0) * 4);
        fma_row<2>(acc, a.y, wbase + (k4 * 4 + 1) * 4);
        fma_row<2>(acc, a.z, wbase + (k4 * 4 + 2) * 4);
        fma_row<2>(acc, a.w, wbase + (k4 * 4 + 3) * 4);
    }
    union { __half2 h[4]; uint4 u; } pk;
#pragma unroll
    for (int j = 0; j < 2; j++) {
        float4 v = make_float4(acc[j].x * dv, acc[j].y * dv, acc[j].z * dv, acc[j].w * dv);
        g_oacc[row * 4 + half * 2 + j] = v;
        pk.h[j * 2 + 0] = __floats2half2_rn(v.x, v.y);
        pk.h[j * 2 + 1] = __floats2half2_rn(v.z, v.w);
    }
    *(uint4*)&g_h2s16[row * 8 + half * 4] = pk.u;
}

// ---------------- edge scatter, layer 2 (4 lanes/edge, 8B fp16 gather) ----
__global__ void __launch_bounds__(256) scatter2_kernel(const int* __restrict__ e32,
                                                       int E) {
    bool is64 = detect64(e32);
    int lane = threadIdx.x & 31;
    int warp = (blockIdx.x * blockDim.x + threadIdx.x) >> 5;
    int base = warp * 32;
    if (base >= E) return;
    int ed = base + lane;
    int edc = ed < E ? ed : E - 1;
    int r_l = load_idx(e32, edc, is64);
    int c_l = load_idx2(e32, E, edc, is64);
    int q = lane & 3;
    int sub = lane >> 2;
#pragma unroll
    for (int j = 0; j < 4; j++) {
        int e0 = 8 * j + sub;
        int rr = __shfl_sync(0xffffffffu, r_l, e0);
        int cc = __shfl_sync(0xffffffffu, c_l, e0);
        if (base + e0 < E) {
            uint2 u = __ldg((const uint2*)&g_h2s16[rr * 8 + 2 * q]);
            __half2 h0 = *(__half2*)&u.x;
            __half2 h1 = *(__half2*)&u.y;
            float2 f0 = __half22float2(h0);
            float2 f1 = __half22float2(h1);
            red4(&g_oacc[cc * 4 + q], make_float4(f0.x, f0.y, f1.x, f1.y));
        }
    }
}

// finalize: out = oacc*dinv + b2 ; also reset g_deg for the next replay.
__global__ void __launch_bounds__(256) finalize_kernel(const float* __restrict__ b2,
                                                       float4* __restrict__ out4) {
    int t = blockIdx.x * blockDim.x + threadIdx.x;
    if (t >= NN * 4) return;
    if (t < NN) g_deg[t] = 0u;
    float dv = __ldg(&g_dinv[t >> 2]);
    float4 a = g_oacc[t];
    float4 bv = __ldg(&((const float4*)b2)[t & 3]);
    out4[t] = make_float4(fmaf(a.x, dv, bv.x), fmaf(a.y, dv, bv.y),
                          fmaf(a.z, dv, bv.z), fmaf(a.w, dv, bv.w));
}

// ---------------- launch ----------------
extern "C" void kernel_launch(void* const* d_in, const int* in_sizes, int n_in,
                              void* d_out, int out_size) {
    const float* x = (const float*)d_in[0];
    const int* e32 = (const int*)d_in[1];
    const float* W1 = (const float*)d_in[2];
    const float* b1 = (const float*)d_in[3];
    const float* W2 = (const float*)d_in[4];
    const float* b2 = (const float*)d_in[5];
    int E = in_sizes[1] / 2;

    deg_count_kernel<<<(E + 255) / 256, 256>>>(e32, E);
    mm1_kernel<<<(NN * 2 + 255) / 256, 256>>>((const float4*)x, W1);
    {
        int nthreads = ((E + 31) / 32) * 32;
        scatter1_kernel<<<(nthreads + 255) / 256, 256>>>(e32, E);
    }
    mm2_kernel<<<(NN * 2 + 255) / 256, 256>>>(W2, b1);
    {
        int nthreads = ((E + 31) / 32) * 32;
        scatter2_kernel<<<(nthreads + 255) / 256, 256>>>(e32, E);
    }
    finalize_kernel<<<(NN * 4 + 255) / 256, 256>>>(b2, (float4*)d_out);
}